// round 16
// baseline (speedup 1.0000x reference)
#include <cuda_runtime.h>
#include <cuda_fp16.h>
#include <math.h>
#include <stdint.h>

#define N_BATCH 4
#define CIN     512
#define COUT    512
#define HWPIX   4096
#define NA      36864
#define NPRE    6000
#define NPOST   300
#define NCHUNK  94
#define NPAD    6016
#define SORTN   8192
#define PADPX   4356      // 66*66
#define NTILE   1024
#define GTILE   4096

#define LOCS_OFF   0
#define SCORES_OFF 589824
#define ROIS_OFF   884736
#define RIND_OFF   889536
#define ANCH_OFF   890736

#define STAGE_BYTES  27648
#define MASTER_OFF_F (128 + 2 * STAGE_BYTES / 4)
#define CONV_SMEM    88576

// ---------------- scratch ----------------
__device__ float               g_xt[(size_t)N_BATCH * PADPX * CIN];
__device__ __half              g_V[(size_t)2 * 16 * GTILE * CIN];
__device__ __half              g_U[(size_t)2 * 16 * COUT * CIN];
__device__ float               g_M[(size_t)16 * GTILE * COUT];
__device__ float               g_hp[(size_t)N_BATCH * HWPIX * COUT];
__device__ float               g_fg[N_BATCH * NA];
__device__ float4              g_boxes[N_BATCH * NA];
__device__ unsigned            g_keys[N_BATCH * NA];
__device__ unsigned            g_cut[N_BATCH];
__device__ int                 g_cnt[N_BATCH];
__device__ unsigned long long  g_sel[N_BATCH][SORTN];
__device__ float4              g_bsort[N_BATCH][NPAD];
__device__ unsigned long long  g_masks[N_BATCH][NPAD][NCHUNK];

// ---------------- helpers ----------------
__device__ __forceinline__ uint32_t smem_u32(const void* p) {
    uint32_t a;
    asm("{ .reg .u64 t; cvta.to.shared.u64 t, %1; cvt.u32.u64 %0, t; }" : "=r"(a) : "l"(p));
    return a;
}
__device__ __forceinline__ unsigned f2key(float f) {
    unsigned u = __float_as_uint(f);
    return (u & 0x80000000u) ? ~u : (u | 0x80000000u);
}
__device__ __forceinline__ void anchor_base(int a, float* out) {
    const double ratios[3] = {0.5, 1.0, 2.0};
    const double scales[3] = {8.0, 16.0, 32.0};
    int ri = a / 3, si = a % 3;
    double h = 16.0 * scales[si] * sqrt(ratios[ri]);
    double w = 16.0 * scales[si] * sqrt(1.0 / ratios[ri]);
    out[0] = (float)(8.0 - h * 0.5);
    out[1] = (float)(8.0 - w * 0.5);
    out[2] = (float)(8.0 + h * 0.5);
    out[3] = (float)(8.0 + w * 0.5);
}

// ---------------- init ----------------
__global__ void init_k() {
    int idx = blockIdx.x * 256 + threadIdx.x;
    if (idx < N_BATCH) g_cnt[idx] = 0;
    if (idx < N_BATCH * SORTN) (&g_sel[0][0])[idx] = 0ull;
}

__global__ void xborder_k() {
    int idx = blockIdx.x * 256 + threadIdx.x;
    int total = 260 * 512;
    if (idx >= total * N_BATCH) return;
    int n = idx / total;
    int r = idx - n * total;
    int b = r >> 9, ic = r & 511;
    int prow;
    if (b < 66)        prow = b;
    else if (b < 132)  prow = 65 * 66 + (b - 66);
    else if (b < 196)  prow = (b - 132 + 1) * 66;
    else               prow = (b - 196 + 1) * 66 + 65;
    g_xt[((size_t)n * PADPX + prow) * CIN + ic] = 0.f;
}

__global__ __launch_bounds__(256) void xt_k(const float* __restrict__ x) {
    __shared__ float s[64][65];
    int row = blockIdx.x, ic0 = blockIdx.y * 64, n = blockIdx.z;
    int tid = threadIdx.x;
    #pragma unroll
    for (int k = 0; k < 16; k++) {
        int idx = tid + k * 256;
        int ic_l = idx >> 6, p = idx & 63;
        s[ic_l][p] = x[((size_t)(n * CIN + ic0 + ic_l) << 12) + row * 64 + p];
    }
    __syncthreads();
    #pragma unroll
    for (int k = 0; k < 16; k++) {
        int idx = tid + k * 256;
        int p = idx >> 6, ic_l = idx & 63;
        int prow = (row + 1) * 66 + (p + 1);
        g_xt[((size_t)n * PADPX + prow) * CIN + ic0 + ic_l] = s[ic_l][p];
    }
}

__global__ void uwino_k(const float* __restrict__ W1) {
    int e = blockIdx.x * 256 + threadIdx.x;
    if (e >= COUT * CIN) return;
    int oc = e >> 9, ic = e & 511;
    float g[3][3];
    #pragma unroll
    for (int t = 0; t < 9; t++) g[t / 3][t % 3] = W1[((size_t)oc * CIN + ic) * 9 + t];
    float r[4][3];
    #pragma unroll
    for (int k = 0; k < 3; k++) {
        r[0][k] = g[0][k];
        r[1][k] = 0.5f * (g[0][k] + g[1][k] + g[2][k]);
        r[2][k] = 0.5f * (g[0][k] - g[1][k] + g[2][k]);
        r[3][k] = g[2][k];
    }
    #pragma unroll
    for (int i = 0; i < 4; i++) {
        float U0 = r[i][0];
        float U1 = 0.5f * (r[i][0] + r[i][1] + r[i][2]);
        float U2 = 0.5f * (r[i][0] - r[i][1] + r[i][2]);
        float U3 = r[i][2];
        float Uv[4] = {U0, U1, U2, U3};
        #pragma unroll
        for (int j = 0; j < 4; j++) {
            int u = i * 4 + j;
            __half hi = __float2half(Uv[j]);
            float lo = (Uv[j] - __half2float(hi)) * 4096.f;
            size_t o = ((size_t)u * COUT + oc) * CIN + ic;
            g_U[o] = hi;
            g_U[o + (size_t)16 * COUT * CIN] = __float2half(lo);
        }
    }
}

__global__ __launch_bounds__(256) void vwino_k() {
    int tile = blockIdx.x, n = blockIdx.z;
    int ic = blockIdx.y * 256 + threadIdx.x;
    int ty = tile >> 5, tx = tile & 31;
    int gtile = n * NTILE + tile;
    float d[4][4];
    #pragma unroll
    for (int i = 0; i < 4; i++)
        #pragma unroll
        for (int j = 0; j < 4; j++)
            d[i][j] = g_xt[((size_t)n * PADPX + (2 * ty + i) * 66 + 2 * tx + j) * CIN + ic];
    float t[4][4];
    #pragma unroll
    for (int j = 0; j < 4; j++) {
        t[0][j] = d[0][j] - d[2][j];
        t[1][j] = d[1][j] + d[2][j];
        t[2][j] = d[2][j] - d[1][j];
        t[3][j] = d[1][j] - d[3][j];
    }
    #pragma unroll
    for (int i = 0; i < 4; i++) {
        float V0 = t[i][0] - t[i][2];
        float V1 = t[i][1] + t[i][2];
        float V2 = t[i][2] - t[i][1];
        float V3 = t[i][1] - t[i][3];
        float Vv[4] = {V0, V1, V2, V3};
        #pragma unroll
        for (int j = 0; j < 4; j++) {
            int u = i * 4 + j;
            __half hi = __float2half(Vv[j]);
            float lo = (Vv[j] - __half2float(hi)) * 4096.f;
            size_t o = ((size_t)u * GTILE + gtile) * CIN + ic;
            g_V[o] = hi;
            g_V[o + (size_t)16 * GTILE * CIN] = __float2half(lo);
        }
    }
}

// ---------------- winograd-domain GEMM ----------------
__device__ __forceinline__ void wino_issue(int iter, uint32_t dstbase,
                                           int tid, int mb, int ocb, int u) {
    int term = iter >> 3;
    int icc = (iter & 7) * 64;
    int sAs = (term == 2) ? 1 : 0;
    int sBs = (term == 1) ? 1 : 0;
    const __half* vbase = g_V + (size_t)sAs * 16 * GTILE * CIN
                        + ((size_t)u * GTILE + mb * 64) * CIN + icc;
    #pragma unroll
    for (int r = 0; r < 2; r++) {
        int idx = tid + r * 256;
        int arow = idx >> 3, q = idx & 7;
        const __half* src = vbase + (size_t)arow * CIN + q * 8;
        uint32_t dst = dstbase + (uint32_t)(arow * 144 + q * 16);
        asm volatile("cp.async.cg.shared.global [%0], [%1], 16;" :: "r"(dst), "l"(src));
    }
    const __half* ubase = g_U + (size_t)sBs * 16 * COUT * CIN
                        + ((size_t)u * COUT + ocb * 128) * CIN + icc;
    #pragma unroll
    for (int r = 0; r < 4; r++) {
        int idx = tid + r * 256;
        int brow = idx >> 3, q = idx & 7;
        const __half* src = ubase + (size_t)brow * CIN + q * 8;
        uint32_t dst = dstbase + (uint32_t)(9216 + brow * 144 + q * 16);
        asm volatile("cp.async.cg.shared.global [%0], [%1], 16;" :: "r"(dst), "l"(src));
    }
}

__global__ __launch_bounds__(256, 2) void wino_mma_k() {
    extern __shared__ float dyn[];
    char* sStage = (char*)(dyn + 128);
    float* sMaster = dyn + MASTER_OFF_F;
    uint32_t bufu = smem_u32(sStage);
    int tid = threadIdx.x, lane = tid & 31, warp = tid >> 5;
    int g = lane >> 2, tig = lane & 3;
    int warpm = warp & 1, warpn = warp >> 1;
    int mb = blockIdx.x, ocb = blockIdx.y, u = blockIdx.z;

    float work[2][4][4] = {};

    wino_issue(0, bufu, tid, mb, ocb, u);
    asm volatile("cp.async.commit_group;" ::: "memory");

    for (int iter = 0; iter < 24; iter++) {
        asm volatile("cp.async.wait_group 0;" ::: "memory");
        __syncthreads();
        if (iter + 1 < 24) {
            wino_issue(iter + 1, bufu + (uint32_t)((iter + 1) & 1) * STAGE_BYTES,
                       tid, mb, ocb, u);
            asm volatile("cp.async.commit_group;" ::: "memory");
        }
        const uint32_t* sA = (const uint32_t*)(sStage + (iter & 1) * STAGE_BYTES);
        const uint32_t* sB = sA + 2304;

        #pragma unroll
        for (int ks = 0; ks < 4; ks++) {
            int kw = ks * 8;
            uint32_t a[2][4];
            #pragma unroll
            for (int mt = 0; mt < 2; mt++) {
                int base = warpm * 32 + mt * 16;
                a[mt][0] = sA[(base + g) * 36 + kw + tig];
                a[mt][1] = sA[(base + g + 8) * 36 + kw + tig];
                a[mt][2] = sA[(base + g) * 36 + kw + 4 + tig];
                a[mt][3] = sA[(base + g + 8) * 36 + kw + 4 + tig];
            }
            #pragma unroll
            for (int nt = 0; nt < 4; nt++) {
                int col = warpn * 32 + nt * 8 + g;
                uint32_t b0 = sB[col * 36 + kw + tig];
                uint32_t b1 = sB[col * 36 + kw + 4 + tig];
                #pragma unroll
                for (int mt = 0; mt < 2; mt++) {
                    asm volatile(
                        "mma.sync.aligned.m16n8k16.row.col.f32.f16.f16.f32 "
                        "{%0,%1,%2,%3}, {%4,%5,%6,%7}, {%8,%9}, {%0,%1,%2,%3};"
                        : "+f"(work[mt][nt][0]), "+f"(work[mt][nt][1]),
                          "+f"(work[mt][nt][2]), "+f"(work[mt][nt][3])
                        : "r"(a[mt][0]), "r"(a[mt][1]), "r"(a[mt][2]), "r"(a[mt][3]),
                          "r"(b0), "r"(b1));
                }
            }
        }
        if ((iter & 3) == 3) {
            bool first = (iter == 3);
            bool corr = (iter >= 8);
            float sc = corr ? (1.f / 4096.f) : 1.f;
            #pragma unroll
            for (int mt = 0; mt < 2; mt++)
                #pragma unroll
                for (int nt = 0; nt < 4; nt++)
                    #pragma unroll
                    for (int q = 0; q < 4; q++) {
                        int e = ((mt * 4) + nt) * 4 + q;
                        float w = work[mt][nt][q] * sc;
                        if (first) sMaster[e * 256 + tid] = w;
                        else       sMaster[e * 256 + tid] += w;
                        work[mt][nt][q] = 0.f;
                    }
        }
    }
    __syncthreads();

    size_t mbase = (size_t)u * GTILE * COUT;
    #pragma unroll
    for (int mt = 0; mt < 2; mt++) {
        int tile = mb * 64 + warpm * 32 + mt * 16 + g;
        #pragma unroll
        for (int nt = 0; nt < 4; nt++) {
            int oc = ocb * 128 + warpn * 32 + nt * 8 + 2 * tig;
            int e = ((mt * 4) + nt) * 4;
            g_M[mbase + (size_t)tile * COUT + oc]           = sMaster[(e + 0) * 256 + tid];
            g_M[mbase + (size_t)tile * COUT + oc + 1]       = sMaster[(e + 1) * 256 + tid];
            g_M[mbase + (size_t)(tile + 8) * COUT + oc]     = sMaster[(e + 2) * 256 + tid];
            g_M[mbase + (size_t)(tile + 8) * COUT + oc + 1] = sMaster[(e + 3) * 256 + tid];
        }
    }
}

// output transform
__global__ __launch_bounds__(512) void owino_k(const float* __restrict__ bias) {
    int tile = blockIdx.x, n = blockIdx.y;
    int oc = threadIdx.x;
    int ty = tile >> 5, tx = tile & 31;
    int gtile = n * NTILE + tile;
    float m[16];
    #pragma unroll
    for (int u = 0; u < 16; u++)
        m[u] = g_M[((size_t)u * GTILE + gtile) * COUT + oc];
    float t[2][4];
    #pragma unroll
    for (int j = 0; j < 4; j++) {
        t[0][j] = m[0 * 4 + j] + m[1 * 4 + j] + m[2 * 4 + j];
        t[1][j] = m[1 * 4 + j] - m[2 * 4 + j] - m[3 * 4 + j];
    }
    float bv = bias[oc];
    #pragma unroll
    for (int i = 0; i < 2; i++) {
        float y0 = t[i][0] + t[i][1] + t[i][2] + bv;
        float y1 = t[i][1] - t[i][2] - t[i][3] + bv;
        int py = 2 * ty + i;
        size_t b = ((size_t)n * HWPIX + py * 64 + 2 * tx) * COUT + oc;
        g_hp[b]        = fmaxf(y0, 0.f);
        g_hp[b + COUT] = fmaxf(y1, 0.f);
    }
}

// ---------------- fused 1x1 heads + fg softmax ----------------
__global__ __launch_bounds__(256) void heads_k(const float* __restrict__ Wl,
                                               const float* __restrict__ bl,
                                               const float* __restrict__ Ws,
                                               const float* __restrict__ bs,
                                               float* __restrict__ dout) {
    int n = blockIdx.y;
    int p0 = blockIdx.x * 64;
    int tid = threadIdx.x;
    int pxg = tid & 15, cg = tid >> 4;
    int px0 = pxg * 4, c0 = cg * 4;

    __shared__ float sH[64][65];
    __shared__ float sWc[64][64];

    float acc[4][4] = {};

    for (int icc = 0; icc < CIN; icc += 64) {
        for (int idx = tid; idx < 4096; idx += 256) {
            int p = idx >> 6, ic = idx & 63;
            sH[ic][p] = g_hp[((size_t)n * HWPIX + p0 + p) * COUT + icc + ic];
        }
        for (int idx = tid; idx < 4096; idx += 256) {
            int ic = idx >> 6, c = idx & 63;
            float w = 0.f;
            if (c < 36)      w = Wl[(size_t)c * CIN + icc + ic];
            else if (c < 54) w = Ws[(size_t)(c - 36) * CIN + icc + ic];
            sWc[ic][c] = w;
        }
        __syncthreads();
        #pragma unroll 16
        for (int ic = 0; ic < 64; ic++) {
            float w0 = sWc[ic][c0 + 0], w1 = sWc[ic][c0 + 1];
            float w2 = sWc[ic][c0 + 2], w3 = sWc[ic][c0 + 3];
            float v0 = sH[ic][px0 + 0], v1 = sH[ic][px0 + 1];
            float v2 = sH[ic][px0 + 2], v3 = sH[ic][px0 + 3];
            acc[0][0] += w0 * v0; acc[0][1] += w0 * v1; acc[0][2] += w0 * v2; acc[0][3] += w0 * v3;
            acc[1][0] += w1 * v0; acc[1][1] += w1 * v1; acc[1][2] += w1 * v2; acc[1][3] += w1 * v3;
            acc[2][0] += w2 * v0; acc[2][1] += w2 * v1; acc[2][2] += w2 * v2; acc[2][3] += w2 * v3;
            acc[3][0] += w3 * v0; acc[3][1] += w3 * v1; acc[3][2] += w3 * v2; acc[3][3] += w3 * v3;
        }
        __syncthreads();
    }

    float val[4][4];
    #pragma unroll
    for (int ci = 0; ci < 4; ci++) {
        int cc = c0 + ci;
        float bv = (cc < 36) ? bl[cc] : ((cc < 54) ? bs[cc - 36] : 0.f);
        #pragma unroll
        for (int pi = 0; pi < 4; pi++) val[ci][pi] = acc[ci][pi] + bv;
    }
    #pragma unroll
    for (int ci = 0; ci < 4; ci++) {
        int cc = c0 + ci;
        #pragma unroll
        for (int pi = 0; pi < 4; pi++) {
            int p = p0 + px0 + pi;
            if (cc < 36)
                dout[LOCS_OFF + (size_t)n * 147456 + (size_t)p * 36 + cc] = val[ci][pi];
            else if (cc < 54)
                dout[SCORES_OFF + (size_t)n * 73728 + (size_t)p * 18 + (cc - 36)] = val[ci][pi];
        }
    }
    if (c0 >= 36 && c0 < 54) {
        #pragma unroll
        for (int pr = 0; pr < 2; pr++) {
            int ce = c0 + 2 * pr;
            if (ce + 1 < 54) {
                int a = (ce - 36) >> 1;
                #pragma unroll
                for (int pi = 0; pi < 4; pi++) {
                    float d = val[2 * pr + 1][pi] - val[2 * pr][pi];
                    float fg = 1.f / (1.f + expf(-d));
                    g_fg[n * NA + (p0 + px0 + pi) * 9 + a] = fg;
                }
            }
        }
    }
}

// ---------------- anchors ----------------
__global__ void anchors_k(float* __restrict__ dout) {
    int j = blockIdx.x * 256 + threadIdx.x;
    if (j >= NA) return;
    int p = j / 9, a = j % 9;
    int y = p >> 6, xx = p & 63;
    float ab[4];
    anchor_base(a, ab);
    float* o = dout + ANCH_OFF + (size_t)j * 4;
    o[0] = y * 16.f + ab[0];
    o[1] = xx * 16.f + ab[1];
    o[2] = y * 16.f + ab[2];
    o[3] = xx * 16.f + ab[3];
}

// ---------------- loc2bbox + clip + min-size + key ----------------
__global__ void boxes_k(const float* __restrict__ dout,
                        const int* __restrict__ pih, const int* __restrict__ piw) {
    int idx = blockIdx.x * 256 + threadIdx.x;
    if (idx >= N_BATCH * NA) return;
    int n = idx / NA, j = idx - n * NA;
    int p = j / 9, a = j - p * 9;
    int y = p >> 6, xx = p & 63;
    float ab[4];
    anchor_base(a, ab);
    float a0 = y * 16.f + ab[0], a1 = xx * 16.f + ab[1];
    float a2 = y * 16.f + ab[2], a3 = xx * 16.f + ab[3];

    const float* loc = dout + LOCS_OFF + (size_t)n * 147456 + (size_t)j * 4;
    float dy = loc[0], dx = loc[1], dh = loc[2], dw = loc[3];

    float src_h = a2 - a0, src_w = a3 - a1;
    float ctr_y = a0 + 0.5f * src_h, ctr_x = a1 + 0.5f * src_w;
    float cy = dy * src_h + ctr_y;
    float cx = dx * src_w + ctr_x;
    float hh = expf(dh) * src_h;
    float ww = expf(dw) * src_w;

    float fh = (float)(*pih), fw = (float)(*piw);
    float y1 = fminf(fmaxf(cy - 0.5f * hh, 0.f), fh);
    float y2 = fminf(fmaxf(cy + 0.5f * hh, 0.f), fh);
    float x1 = fminf(fmaxf(cx - 0.5f * ww, 0.f), fw);
    float x2 = fminf(fmaxf(cx + 0.5f * ww, 0.f), fw);

    bool valid = ((y2 - y1) >= 16.f) && ((x2 - x1) >= 16.f);
    float sc = valid ? g_fg[idx] : -INFINITY;

    g_boxes[idx] = make_float4(y1, x1, y2, x2);
    g_keys[idx] = f2key(sc);
}

// ---------------- radix select ----------------
__global__ __launch_bounds__(1024) void select_k() {
    int n = blockIdx.x;
    const unsigned* keys = g_keys + (size_t)n * NA;
    __shared__ unsigned hist[256];
    __shared__ unsigned sprefix;
    __shared__ int srem;
    if (threadIdx.x == 0) { sprefix = 0u; srem = NPRE; }
    __syncthreads();
    for (int pass = 0; pass < 4; pass++) {
        for (int b = threadIdx.x; b < 256; b += 1024) hist[b] = 0u;
        __syncthreads();
        int shift = 24 - 8 * pass;
        unsigned maskhi = pass ? (0xFFFFFFFFu << (32 - 8 * pass)) : 0u;
        unsigned pref = sprefix;
        for (int i = threadIdx.x; i < NA; i += 1024) {
            unsigned k = keys[i];
            if ((k & maskhi) == pref) atomicAdd(&hist[(k >> shift) & 0xFF], 1u);
        }
        __syncthreads();
        if (threadIdx.x == 0) {
            unsigned cum = 0;
            int rem = srem;
            for (int b = 255; b >= 0; b--) {
                cum += hist[b];
                if ((int)cum >= rem) {
                    srem = rem - (int)(cum - hist[b]);
                    sprefix = pref | ((unsigned)b << shift);
                    break;
                }
            }
        }
        __syncthreads();
    }
    if (threadIdx.x == 0) g_cut[n] = sprefix;
}

// ---------------- compact ----------------
__global__ void compact_k() {
    int idx = blockIdx.x * 256 + threadIdx.x;
    if (idx >= N_BATCH * NA) return;
    int n = idx / NA;
    unsigned k = g_keys[idx];
    if (k >= g_cut[n]) {
        int pos = atomicAdd(&g_cnt[n], 1);
        if (pos < SORTN) {
            unsigned j = (unsigned)(idx - n * NA);
            g_sel[n][pos] = ((unsigned long long)k << 32) | (0xFFFFFFFFu - j);
        }
    }
}

// ---------------- bitonic sort + gather ----------------
__global__ __launch_bounds__(1024) void sort_k() {
    int n = blockIdx.x;
    extern __shared__ unsigned long long sh[];
    for (int i = threadIdx.x; i < SORTN; i += 1024) sh[i] = g_sel[n][i];
    __syncthreads();
    for (int k = 2; k <= SORTN; k <<= 1) {
        for (int j = k >> 1; j > 0; j >>= 1) {
            for (int i = threadIdx.x; i < SORTN; i += 1024) {
                int ixj = i ^ j;
                if (ixj > i) {
                    unsigned long long a = sh[i], b = sh[ixj];
                    bool up = (i & k) == 0;
                    if (up ? (a < b) : (a > b)) { sh[i] = b; sh[ixj] = a; }
                }
            }
            __syncthreads();
        }
    }
    for (int r = threadIdx.x; r < NPRE; r += 1024) {
        unsigned long long comp = sh[r];
        unsigned j = 0xFFFFFFFFu - (unsigned)(comp & 0xFFFFFFFFull);
        if (j >= NA) j = NA - 1;
        g_bsort[n][r] = g_boxes[(size_t)n * NA + j];
    }
}

// ---------------- NMS masks: one 256-thread block per (ci, n), 4 cj chunks per iter ----------------
__global__ __launch_bounds__(256) void masks_k() {
    int ci = blockIdx.x, n = blockIdx.y;
    int t = threadIdx.x;
    int ti = t & 63;          // i within chunk
    int cjo = t >> 6;         // 0..3: cj lane
    __shared__ float4 sbj[4][64];

    int i = ci * 64 + ti;
    bool ivalid = i < NPRE;
    float4 bi = make_float4(0.f, 0.f, 0.f, 0.f);
    float areai = 0.f;
    if (ivalid) {
        bi = g_bsort[n][i];
        areai = (bi.z - bi.x) * (bi.w - bi.y);
    }

    // zero lower-triangle chunks (read unconditionally by nms reduction)
    for (int cj = cjo; cj < ci; cj += 4) g_masks[n][i][cj] = 0ull;

    for (int cjb = ci; cjb < NCHUNK; cjb += 4) {
        int cj = cjb + cjo;
        {
            int jg = cj * 64 + ti;
            sbj[cjo][ti] = (cj < NCHUNK && jg < NPRE) ? g_bsort[n][jg]
                                                      : make_float4(0.f, 0.f, 0.f, 0.f);
        }
        __syncthreads();
        if (cj < NCHUNK) {
            unsigned long long m = 0ull;
            if (ivalid) {
                int jbase = cj * 64;
                #pragma unroll 8
                for (int jj = 0; jj < 64; jj++) {
                    int jgl = jbase + jj;
                    if (jgl > i && jgl < NPRE) {
                        float4 bb = sbj[cjo][jj];
                        float ty1 = fmaxf(bi.x, bb.x), tx1 = fmaxf(bi.y, bb.y);
                        float ty2 = fminf(bi.z, bb.z), tx2 = fminf(bi.w, bb.w);
                        float ihh = fmaxf(ty2 - ty1, 0.f), iww = fmaxf(tx2 - tx1, 0.f);
                        float inter = ihh * iww;
                        float areaj = (bb.z - bb.x) * (bb.w - bb.y);
                        float iou = inter / (areai + areaj - inter + 1e-10f);
                        if (iou > 0.7f) m |= (1ull << jj);
                    }
                }
            }
            g_masks[n][i][cj] = m;
        }
        __syncthreads();
    }
}

// ---------------- single-warp NMS: depth-32 diagonal prefetch, boundary-only shfl ----------------
__global__ __launch_bounds__(32) void nms_emit_k(float* __restrict__ dout) {
    int n = blockIdx.x;
    int l = threadIdx.x;
    int c0 = l, c1 = l + 32, c2 = l + 64;
    bool v2 = c2 < NCHUNK;
    unsigned long long rv0 = 0, rv1 = 0, rv2 = 0;
    unsigned long long b0[8], b1[8], b2[8], mbuf[32];
    #pragma unroll
    for (int s = 0; s < 8; s++) {
        b0[s] = g_masks[n][s][c0];
        b1[s] = g_masks[n][s][c1];
        b2[s] = v2 ? g_masks[n][s][c2] : 0ull;
    }
    #pragma unroll
    for (int s = 0; s < 32; s++) mbuf[s] = g_masks[n][s][0];
    unsigned long long cur = 0ull;
    for (int ib = 0; ib < NPAD; ib += 32) {
        #pragma unroll
        for (int s = 0; s < 32; s++) {
            int i = ib + s;
            unsigned long long cm0 = b0[s & 7], cm1 = b1[s & 7], cm2 = b2[s & 7];
            unsigned long long m = mbuf[s];
            if (i + 8 < NPAD) {
                b0[s & 7] = g_masks[n][i + 8][c0];
                b1[s & 7] = g_masks[n][i + 8][c1];
                b2[s & 7] = v2 ? g_masks[n][i + 8][c2] : 0ull;
            }
            if (i + 32 < NPAD) mbuf[s] = g_masks[n][i + 32][(i + 32) >> 6];
            if ((i & 63) == 0) {
                int ch = i >> 6, slot = ch >> 5, src = ch & 31;
                unsigned long long rsel = (slot == 0) ? rv0 : ((slot == 1) ? rv1 : rv2);
                cur = __shfl_sync(0xFFFFFFFFu, rsel, src);
            }
            if (i < NPRE && !((cur >> (i & 63)) & 1ull)) {
                rv0 |= cm0; rv1 |= cm1; rv2 |= cm2;
                cur |= m;
            }
        }
    }
    __shared__ unsigned long long remv[96];
    remv[l] = rv0; remv[l + 32] = rv1;
    if (v2) remv[l + 64] = rv2;
    __syncwarp();
    float* rind = dout + RIND_OFF + n * NPOST;
    for (int q = l; q < NPOST; q += 32) rind[q] = (float)n;
    if (l == 0) {
        float4* rois = (float4*)(dout + ROIS_OFF) + n * NPOST;
        int r = 0;
        for (int i = 0; i < NPRE && r < NPOST; i++)
            if (((remv[i >> 6] >> (i & 63)) & 1ull) == 0ull) rois[r++] = g_bsort[n][i];
        for (int i = 0; i < NPRE && r < NPOST; i++)
            if (((remv[i >> 6] >> (i & 63)) & 1ull) != 0ull) rois[r++] = g_bsort[n][i];
    }
}

// ---------------- launch ----------------
extern "C" void kernel_launch(void* const* d_in, const int* in_sizes, int n_in,
                              void* d_out, int out_size) {
    const float* x  = (const float*)d_in[0];
    const float* W1 = (const float*)d_in[1];
    const float* b1 = (const float*)d_in[2];
    const float* Ws = (const float*)d_in[3];
    const float* bs = (const float*)d_in[4];
    const float* Wl = (const float*)d_in[5];
    const float* bl = (const float*)d_in[6];
    const int* ih   = (const int*)d_in[7];
    const int* iw   = (const int*)d_in[8];
    float* out = (float*)d_out;

    cudaFuncSetAttribute(sort_k, cudaFuncAttributeMaxDynamicSharedMemorySize, SORTN * 8);
    cudaFuncSetAttribute(wino_mma_k, cudaFuncAttributeMaxDynamicSharedMemorySize, CONV_SMEM);

    init_k<<<(N_BATCH * SORTN + 255) / 256, 256>>>();
    xborder_k<<<(260 * 512 * N_BATCH + 255) / 256, 256>>>();
    xt_k<<<dim3(64, 8, 4), 256>>>(x);
    uwino_k<<<(COUT * CIN + 255) / 256, 256>>>(W1);
    vwino_k<<<dim3(NTILE, 2, 4), 256>>>();
    wino_mma_k<<<dim3(64, 4, 16), 256, CONV_SMEM>>>();
    owino_k<<<dim3(NTILE, 4), 512>>>(b1);
    heads_k<<<dim3(64, 4), 256>>>(Wl, bl, Ws, bs, out);
    anchors_k<<<(NA + 255) / 256, 256>>>(out);
    boxes_k<<<(N_BATCH * NA + 255) / 256, 256>>>(out, ih, iw);
    select_k<<<N_BATCH, 1024>>>();
    compact_k<<<(N_BATCH * NA + 255) / 256, 256>>>();
    sort_k<<<N_BATCH, 1024, SORTN * 8>>>();
    masks_k<<<dim3(NCHUNK, N_BATCH), 256>>>();
    nms_emit_k<<<N_BATCH, 32>>>(out);
}